// round 1
// baseline (speedup 1.0000x reference)
#include <cuda_runtime.h>
#include <math.h>

// ---------------- Problem constants ----------------
#define D_MODEL 1024
#define NHEAD   16
#define HDIM    64        // D_MODEL / NHEAD
#define DFF     4096
#define TM      512
#define TA      512
#define BATCH   32
#define NTOK    (TM * BATCH)   // 16384
#define NBEATS  64
#define LN_EPS  1e-5f

// ---------------- Scratch (device globals; no allocation) ----------------
__device__ float g_qkv [NTOK * 3 * D_MODEL];   // SA packed qkv   (201 MB)
__device__ float g_attn[NTOK * D_MODEL];       // attention output (pre out-proj)
__device__ float g_tmp [NTOK * D_MODEL];       // out-proj result
__device__ float g_x1  [NTOK * D_MODEL];       // after LN1
__device__ float g_q   [NTOK * D_MODEL];       // CA query proj
__device__ float g_kv  [NTOK * 2 * D_MODEL];   // CA key/value proj
__device__ float g_x2  [NTOK * D_MODEL];       // after LN_cross
__device__ float g_ffh [NTOK * DFF];           // FFN hidden (256 MB)
__device__ float g_ff2 [NTOK * D_MODEL];       // FFN output
__device__ float g_bias[TM * TA];              // temporal + beat bias

// ---------------- Bias precompute ----------------
__global__ void bias_kernel(const int* __restrict__ beats, float* __restrict__ out) {
    __shared__ int sb[NBEATS];
    int i = blockIdx.x;       // motion (query) index
    int j = threadIdx.x;      // audio (key) index, blockDim = TA
    if (threadIdx.x < NBEATS) sb[threadIdx.x] = beats[threadIdx.x];
    __syncthreads();
    float bb = 0.0f;
    #pragma unroll 8
    for (int n = 0; n < NBEATS; n++) {
        int bf = sb[n];
        if (j == bf) bb = fmaxf(bb, 2.0f);                 // BW = 2
        if (bf > 0       && j == bf - 1) bb = fmaxf(bb, 1.0f);
        if (bf < TA - 1  && j == bf + 1) bb = fmaxf(bb, 1.0f);
    }
    float scale = (TM > 1 && TA > 1) ? (float)(TA - 1) / (float)(TM - 1) : 1.0f;
    float d = (float)i * scale - (float)j;
    out[i * TA + j] = -(d * d) * (1.0f / 32.0f) + bb;      // 2*sigma^2 = 32
}

// ---------------- SGEMM: C[M,N] = A[M,K] * W[N,K]^T + bias[N]  (optional GELU) ----------------
// A row-major lda=K, W row-major (PyTorch weight layout), C row-major ldc=N.
__global__ __launch_bounds__(256) void sgemm_kernel(
    const float* __restrict__ A, const float* __restrict__ W,
    const float* __restrict__ bias, float* __restrict__ C,
    int M, int N, int K, int act)
{
    __shared__ float As[8][128];
    __shared__ float Bs[8][128];
    int tid = threadIdx.x;
    int bx = blockIdx.x, by = blockIdx.y;
    int lrow = tid >> 1;             // 0..127 (tile row for loads)
    int lcol = (tid & 1) << 2;       // 0 or 4
    const float* Ap = A + (size_t)(by * 128 + lrow) * K + lcol;
    const float* Wp = W + (size_t)(bx * 128 + lrow) * K + lcol;
    int tx = tid & 15, ty = tid >> 4;

    float acc[8][8];
    #pragma unroll
    for (int i = 0; i < 8; i++)
        #pragma unroll
        for (int j = 0; j < 8; j++) acc[i][j] = 0.0f;

    for (int k0 = 0; k0 < K; k0 += 8) {
        float4 a = *(const float4*)(Ap + k0);
        float4 w = *(const float4*)(Wp + k0);
        As[lcol + 0][lrow] = a.x; As[lcol + 1][lrow] = a.y;
        As[lcol + 2][lrow] = a.z; As[lcol + 3][lrow] = a.w;
        Bs[lcol + 0][lrow] = w.x; Bs[lcol + 1][lrow] = w.y;
        Bs[lcol + 2][lrow] = w.z; Bs[lcol + 3][lrow] = w.w;
        __syncthreads();
        #pragma unroll
        for (int kk = 0; kk < 8; kk++) {
            float ar[8], br[8];
            #pragma unroll
            for (int i = 0; i < 4; i++) {
                ar[i]     = As[kk][ty * 4 + i];
                ar[4 + i] = As[kk][64 + ty * 4 + i];
                br[i]     = Bs[kk][tx * 4 + i];
                br[4 + i] = Bs[kk][64 + tx * 4 + i];
            }
            #pragma unroll
            for (int i = 0; i < 8; i++)
                #pragma unroll
                for (int j = 0; j < 8; j++) acc[i][j] += ar[i] * br[j];
        }
        __syncthreads();
    }

    #pragma unroll
    for (int i = 0; i < 8; i++) {
        int m = by * 128 + ((i < 4) ? (ty * 4 + i) : (64 + ty * 4 + (i - 4)));
        #pragma unroll
        for (int j = 0; j < 8; j++) {
            int n = bx * 128 + ((j < 4) ? (tx * 4 + j) : (64 + tx * 4 + (j - 4)));
            float v = acc[i][j] + bias[n];
            if (act) v = 0.5f * v * (1.0f + erff(v * 0.70710678118654752f)); // exact GELU
            C[(size_t)m * N + n] = v;
        }
    }
}

// ---------------- Attention ----------------
// grid: (TM/64, BATCH*NHEAD). Each block: 64 queries x full 512 keys, one (b,h).
// Column layouts: Q at col qbase + h*64 in a (NTOK x ldq) buffer, etc.
#define QS(r, c) Qs[(r) * 65 + (c)]
#define KS(r, c) Ks[(r) * 65 + (c)]
#define SS(r, c) Ss[(r) * 513 + (c)]
#define ATTN_SMEM ((2 * 64 * 65 + 64 * 513) * 4)

__global__ __launch_bounds__(256) void attn_kernel(
    const float* __restrict__ Qb, int ldq, int qbase,
    const float* __restrict__ Kb, int ldk, int kbase,
    const float* __restrict__ Vb, int ldv, int vbase,
    float* __restrict__ Out, const float* __restrict__ bias, float scale)
{
    extern __shared__ float sm[];
    float* Qs = sm;
    float* Ks = sm + 64 * 65;
    float* Ss = sm + 2 * 64 * 65;

    int tid = threadIdx.x;
    int qt = blockIdx.x;
    int bh = blockIdx.y;
    int b = bh & (BATCH - 1);
    int h = bh >> 5;                       // bh / BATCH
    int tx = tid & 15, ty = tid >> 4;

    // Load Q tile (64 x 64)
    for (int p = tid; p < 64 * 16; p += 256) {
        int r = p >> 4, c = (p & 15) << 2;
        float4 v = *(const float4*)(Qb + (size_t)((qt * 64 + r) * BATCH + b) * ldq + qbase + h * HDIM + c);
        QS(r, c) = v.x; QS(r, c + 1) = v.y; QS(r, c + 2) = v.z; QS(r, c + 3) = v.w;
    }

    // Scores: loop over key tiles
    for (int kt = 0; kt < 8; kt++) {
        __syncthreads();
        for (int p = tid; p < 64 * 16; p += 256) {
            int r = p >> 4, c = (p & 15) << 2;
            float4 v = *(const float4*)(Kb + (size_t)((kt * 64 + r) * BATCH + b) * ldk + kbase + h * HDIM + c);
            KS(r, c) = v.x; KS(r, c + 1) = v.y; KS(r, c + 2) = v.z; KS(r, c + 3) = v.w;
        }
        __syncthreads();
        float s[4][4];
        #pragma unroll
        for (int i = 0; i < 4; i++)
            #pragma unroll
            for (int j = 0; j < 4; j++) s[i][j] = 0.0f;
        #pragma unroll 8
        for (int kk = 0; kk < 64; kk++) {
            float qr[4], kr[4];
            #pragma unroll
            for (int i = 0; i < 4; i++) qr[i] = QS(ty * 4 + i, kk);
            #pragma unroll
            for (int j = 0; j < 4; j++) kr[j] = KS(tx * 4 + j, kk);
            #pragma unroll
            for (int i = 0; i < 4; i++)
                #pragma unroll
                for (int j = 0; j < 4; j++) s[i][j] += qr[i] * kr[j];
        }
        #pragma unroll
        for (int i = 0; i < 4; i++) {
            int qg = qt * 64 + ty * 4 + i;
            #pragma unroll
            for (int j = 0; j < 4; j++) {
                int kg = kt * 64 + tx * 4 + j;
                float v = s[i][j] * scale;
                if (bias) v += bias[qg * TA + kg];
                SS(ty * 4 + i, kg) = v;
            }
        }
    }
    __syncthreads();

    // Softmax over 512 keys, one row per warp-iteration
    int w = tid >> 5, lane = tid & 31;
    for (int r = w; r < 64; r += 8) {
        float m = -1e30f;
        for (int c = lane; c < 512; c += 32) m = fmaxf(m, SS(r, c));
        #pragma unroll
        for (int o = 16; o > 0; o >>= 1) m = fmaxf(m, __shfl_xor_sync(0xffffffffu, m, o));
        float sum = 0.0f;
        for (int c = lane; c < 512; c += 32) {
            float e = expf(SS(r, c) - m);
            SS(r, c) = e;
            sum += e;
        }
        #pragma unroll
        for (int o = 16; o > 0; o >>= 1) sum += __shfl_xor_sync(0xffffffffu, sum, o);
        float inv = 1.0f / sum;
        for (int c = lane; c < 512; c += 32) SS(r, c) *= inv;
    }

    // O = P * V
    float acc[4][4];
    #pragma unroll
    for (int i = 0; i < 4; i++)
        #pragma unroll
        for (int j = 0; j < 4; j++) acc[i][j] = 0.0f;

    for (int vt = 0; vt < 8; vt++) {
        __syncthreads();
        for (int p = tid; p < 64 * 16; p += 256) {
            int r = p >> 4, c = (p & 15) << 2;
            float4 v = *(const float4*)(Vb + (size_t)((vt * 64 + r) * BATCH + b) * ldv + vbase + h * HDIM + c);
            KS(r, c) = v.x; KS(r, c + 1) = v.y; KS(r, c + 2) = v.z; KS(r, c + 3) = v.w;
        }
        __syncthreads();
        #pragma unroll 8
        for (int kk = 0; kk < 64; kk++) {
            float pr[4], vr[4];
            #pragma unroll
            for (int i = 0; i < 4; i++) pr[i] = SS(ty * 4 + i, vt * 64 + kk);
            #pragma unroll
            for (int j = 0; j < 4; j++) vr[j] = KS(kk, tx * 4 + j);
            #pragma unroll
            for (int i = 0; i < 4; i++)
                #pragma unroll
                for (int j = 0; j < 4; j++) acc[i][j] += pr[i] * vr[j];
        }
    }
    #pragma unroll
    for (int i = 0; i < 4; i++) {
        int qg = qt * 64 + ty * 4 + i;
        #pragma unroll
        for (int j = 0; j < 4; j++)
            Out[(size_t)(qg * BATCH + b) * D_MODEL + h * HDIM + tx * 4 + j] = acc[i][j];
    }
}

// ---------------- Fused residual + LayerNorm ----------------
// out = LN(a + gscale*b) * gamma + beta;  gscale = tanh(*gatePtr) or 1.
__global__ __launch_bounds__(256) void add_ln_kernel(
    const float* __restrict__ A, const float* __restrict__ Bv,
    const float* __restrict__ gatePtr,
    const float* __restrict__ gamma, const float* __restrict__ beta,
    float* __restrict__ out)
{
    int t = blockIdx.x;
    int tid = threadIdx.x;
    float gscale = gatePtr ? tanhf(*gatePtr) : 1.0f;
    const float4* a4 = (const float4*)(A  + (size_t)t * D_MODEL);
    const float4* b4 = (const float4*)(Bv + (size_t)t * D_MODEL);
    float4 av = a4[tid], bv = b4[tid];
    float x0 = av.x + gscale * bv.x;
    float x1 = av.y + gscale * bv.y;
    float x2 = av.z + gscale * bv.z;
    float x3 = av.w + gscale * bv.w;
    float s  = x0 + x1 + x2 + x3;
    float ss = x0 * x0 + x1 * x1 + x2 * x2 + x3 * x3;

    __shared__ float rs[8], rss[8];
    #pragma unroll
    for (int o = 16; o > 0; o >>= 1) {
        s  += __shfl_xor_sync(0xffffffffu, s,  o);
        ss += __shfl_xor_sync(0xffffffffu, ss, o);
    }
    if ((tid & 31) == 0) { rs[tid >> 5] = s; rss[tid >> 5] = ss; }
    __syncthreads();
    float stot = 0.0f, sstot = 0.0f;
    #pragma unroll
    for (int i = 0; i < 8; i++) { stot += rs[i]; sstot += rss[i]; }
    float mean = stot * (1.0f / D_MODEL);
    float var  = sstot * (1.0f / D_MODEL) - mean * mean;
    float rstd = rsqrtf(var + LN_EPS);

    const float4* g4 = (const float4*)gamma;
    const float4* be4 = (const float4*)beta;
    float4 g = g4[tid], be = be4[tid];
    float4 o;
    o.x = (x0 - mean) * rstd * g.x + be.x;
    o.y = (x1 - mean) * rstd * g.y + be.y;
    o.z = (x2 - mean) * rstd * g.z + be.z;
    o.w = (x3 - mean) * rstd * g.w + be.w;
    ((float4*)(out + (size_t)t * D_MODEL))[tid] = o;
}

// ---------------- Launch ----------------
extern "C" void kernel_launch(void* const* d_in, const int* in_sizes, int n_in,
                              void* d_out, int out_size) {
    const float* src      = (const float*)d_in[0];
    const float* audio    = (const float*)d_in[1];
    const int*   beats    = (const int*)  d_in[2];
    const float* sa_in_w  = (const float*)d_in[3];
    const float* sa_in_b  = (const float*)d_in[4];
    const float* sa_out_w = (const float*)d_in[5];
    const float* sa_out_b = (const float*)d_in[6];
    const float* ca_in_w  = (const float*)d_in[7];
    const float* ca_in_b  = (const float*)d_in[8];
    const float* ca_out_w = (const float*)d_in[9];
    const float* ca_out_b = (const float*)d_in[10];
    const float* gate     = (const float*)d_in[11];
    const float* n1_g     = (const float*)d_in[12];
    const float* n1_b     = (const float*)d_in[13];
    const float* nc_g     = (const float*)d_in[14];
    const float* nc_b     = (const float*)d_in[15];
    const float* n2_g     = (const float*)d_in[16];
    const float* n2_b     = (const float*)d_in[17];
    const float* lin1_w   = (const float*)d_in[18];
    const float* lin1_b   = (const float*)d_in[19];
    const float* lin2_w   = (const float*)d_in[20];
    const float* lin2_b   = (const float*)d_in[21];
    float* out = (float*)d_out;

    float *qkv, *attn, *tmp, *x1, *q, *kv, *x2, *ffh, *ff2, *bias;
    cudaGetSymbolAddress((void**)&qkv,  g_qkv);
    cudaGetSymbolAddress((void**)&attn, g_attn);
    cudaGetSymbolAddress((void**)&tmp,  g_tmp);
    cudaGetSymbolAddress((void**)&x1,   g_x1);
    cudaGetSymbolAddress((void**)&q,    g_q);
    cudaGetSymbolAddress((void**)&kv,   g_kv);
    cudaGetSymbolAddress((void**)&x2,   g_x2);
    cudaGetSymbolAddress((void**)&ffh,  g_ffh);
    cudaGetSymbolAddress((void**)&ff2,  g_ff2);
    cudaGetSymbolAddress((void**)&bias, g_bias);

    cudaFuncSetAttribute(attn_kernel, cudaFuncAttributeMaxDynamicSharedMemorySize, ATTN_SMEM);

    // 0) attention bias (temporal + beat)
    bias_kernel<<<TM, TA>>>(beats, bias);

    // 1) SA: packed QKV projection
    sgemm_kernel<<<dim3(3 * D_MODEL / 128, NTOK / 128), 256>>>(
        src, sa_in_w, sa_in_b, qkv, NTOK, 3 * D_MODEL, D_MODEL, 0);

    // 2) SA attention
    attn_kernel<<<dim3(TM / 64, BATCH * NHEAD), 256, ATTN_SMEM>>>(
        qkv, 3 * D_MODEL, 0,
        qkv, 3 * D_MODEL, D_MODEL,
        qkv, 3 * D_MODEL, 2 * D_MODEL,
        attn, nullptr, 0.125f);

    // 3) SA out-proj
    sgemm_kernel<<<dim3(D_MODEL / 128, NTOK / 128), 256>>>(
        attn, sa_out_w, sa_out_b, tmp, NTOK, D_MODEL, D_MODEL, 0);

    // 4) x1 = LN1(src + sa)
    add_ln_kernel<<<NTOK, 256>>>(src, tmp, nullptr, n1_g, n1_b, x1);

    // 5) CA projections: Q from x1, KV from audio
    sgemm_kernel<<<dim3(D_MODEL / 128, NTOK / 128), 256>>>(
        x1, ca_in_w, ca_in_b, q, NTOK, D_MODEL, D_MODEL, 0);
    sgemm_kernel<<<dim3(2 * D_MODEL / 128, NTOK / 128), 256>>>(
        audio, ca_in_w + (size_t)D_MODEL * D_MODEL, ca_in_b + D_MODEL,
        kv, NTOK, 2 * D_MODEL, D_MODEL, 0);

    // 6) CA attention (with additive bias on scores)
    attn_kernel<<<dim3(TM / 64, BATCH * NHEAD), 256, ATTN_SMEM>>>(
        q,  D_MODEL, 0,
        kv, 2 * D_MODEL, 0,
        kv, 2 * D_MODEL, D_MODEL,
        attn, bias, 0.125f);

    // 7) CA out-proj
    sgemm_kernel<<<dim3(D_MODEL / 128, NTOK / 128), 256>>>(
        attn, ca_out_w, ca_out_b, tmp, NTOK, D_MODEL, D_MODEL, 0);

    // 8) x2 = LNc(x1 + tanh(gate)*cross)
    add_ln_kernel<<<NTOK, 256>>>(x1, tmp, gate, nc_g, nc_b, x2);

    // 9) FFN
    sgemm_kernel<<<dim3(DFF / 128, NTOK / 128), 256>>>(
        x2, lin1_w, lin1_b, ffh, NTOK, DFF, D_MODEL, 1 /*GELU*/);
    sgemm_kernel<<<dim3(D_MODEL / 128, NTOK / 128), 256>>>(
        ffh, lin2_w, lin2_b, ff2, NTOK, D_MODEL, DFF, 0);

    // 10) out = LN2(x2 + ff)
    add_ln_kernel<<<NTOK, 256>>>(x2, ff2, nullptr, n2_g, n2_b, out);
}

// round 4
// speedup vs baseline: 1.7151x; 1.7151x over previous
#include <cuda_runtime.h>
#include <cuda_bf16.h>
#include <math.h>
#include <stdint.h>

// ---------------- Problem constants ----------------
#define D_MODEL 1024
#define NHEAD   16
#define HDIM    64
#define DFF     4096
#define TM      512
#define TA      512
#define BATCH   32
#define NTOK    (TM * BATCH)   // 16384
#define NBEATS  64
#define LN_EPS  1e-5f

// ---------------- fp32 scratch ----------------
__device__ float g_qkv [NTOK * 3 * D_MODEL];
__device__ float g_attn[NTOK * D_MODEL];
__device__ float g_tmp [NTOK * D_MODEL];
__device__ float g_x1  [NTOK * D_MODEL];
__device__ float g_q   [NTOK * D_MODEL];
__device__ float g_kv  [NTOK * 2 * D_MODEL];
__device__ float g_x2  [NTOK * D_MODEL];
__device__ float g_ff2 [NTOK * D_MODEL];
__device__ float g_bias[TM * TA];

// ---------------- bf16 split scratch ----------------
__device__ __nv_bfloat16 g_Xhi[NTOK * D_MODEL];
__device__ __nv_bfloat16 g_Xlo[NTOK * D_MODEL];
__device__ __nv_bfloat16 g_Hhi[NTOK * DFF];
__device__ __nv_bfloat16 g_Hlo[NTOK * DFF];
__device__ __nv_bfloat16 g_Whi[16777216];
__device__ __nv_bfloat16 g_Wlo[16777216];

#define W_SAIN   0u
#define W_SAOUT  3145728u
#define W_CAIN   4194304u
#define W_CAOUT  7340032u
#define W_LIN1   8388608u
#define W_LIN2  12582912u

// ================= helpers (non-'a' PTX only) =================
__device__ __forceinline__ uint32_t smem_u32(const void* p) {
    uint32_t a;
    asm("{ .reg .u64 t; cvta.to.shared.u64 t, %1; cvt.u32.u64 %0, t; }" : "=r"(a) : "l"(p));
    return a;
}
__device__ __forceinline__ void cp_async16(uint32_t saddr, const void* g) {
    asm volatile("cp.async.cg.shared.global [%0], [%1], 16;" :: "r"(saddr), "l"(g));
}
__device__ __forceinline__ void cp_commit() {
    asm volatile("cp.async.commit_group;" ::: "memory");
}
__device__ __forceinline__ void ldsm_x4(uint32_t (&r)[4], uint32_t addr) {
    asm volatile("ldmatrix.sync.aligned.m8n8.x4.shared.b16 {%0,%1,%2,%3}, [%4];"
                 : "=r"(r[0]), "=r"(r[1]), "=r"(r[2]), "=r"(r[3]) : "r"(addr));
}
__device__ __forceinline__ void mma16816(float (&d)[4], const uint32_t (&a)[4],
                                         uint32_t b0, uint32_t b1) {
    asm volatile(
        "mma.sync.aligned.m16n8k16.row.col.f32.bf16.bf16.f32 "
        "{%0,%1,%2,%3}, {%4,%5,%6,%7}, {%8,%9}, {%0,%1,%2,%3};"
        : "+f"(d[0]), "+f"(d[1]), "+f"(d[2]), "+f"(d[3])
        : "r"(a[0]), "r"(a[1]), "r"(a[2]), "r"(a[3]), "r"(b0), "r"(b1));
}

// ================= split-bf16 convert =================
__global__ __launch_bounds__(256) void cvt_kernel(
    const float* __restrict__ src, __nv_bfloat16* __restrict__ hi,
    __nv_bfloat16* __restrict__ lo, int n)
{
    int i = (blockIdx.x * 256 + threadIdx.x) * 4;
    if (i >= n) return;
    float4 v = *(const float4*)(src + i);
    __nv_bfloat16 h0 = __float2bfloat16(v.x), h1 = __float2bfloat16(v.y);
    __nv_bfloat16 h2 = __float2bfloat16(v.z), h3 = __float2bfloat16(v.w);
    __nv_bfloat16 l0 = __float2bfloat16(v.x - __bfloat162float(h0));
    __nv_bfloat16 l1 = __float2bfloat16(v.y - __bfloat162float(h1));
    __nv_bfloat16 l2 = __float2bfloat16(v.z - __bfloat162float(h2));
    __nv_bfloat16 l3 = __float2bfloat16(v.w - __bfloat162float(h3));
    uint2 uh, ul;
    uh.x = (uint32_t)__bfloat16_as_ushort(h0) | ((uint32_t)__bfloat16_as_ushort(h1) << 16);
    uh.y = (uint32_t)__bfloat16_as_ushort(h2) | ((uint32_t)__bfloat16_as_ushort(h3) << 16);
    ul.x = (uint32_t)__bfloat16_as_ushort(l0) | ((uint32_t)__bfloat16_as_ushort(l1) << 16);
    ul.y = (uint32_t)__bfloat16_as_ushort(l2) | ((uint32_t)__bfloat16_as_ushort(l3) << 16);
    *(uint2*)(hi + i) = uh;
    *(uint2*)(lo + i) = ul;
}

// ================= mma.sync GEMM =================
// C[M,N] = A[M,K]*B[N,K]^T + bias, 3-term split-bf16. CTA 128x128, BK=32, 4 stages.
#define G_STAGE 32768
#define G_SMEM  (4 * G_STAGE)

__global__ __launch_bounds__(256, 1) void gemm_mma(
    const __nv_bfloat16* __restrict__ Ahi, const __nv_bfloat16* __restrict__ Alo,
    const __nv_bfloat16* __restrict__ Bhi, const __nv_bfloat16* __restrict__ Blo,
    const float* __restrict__ bias, float* __restrict__ Cf,
    __nv_bfloat16* __restrict__ Ohi, __nv_bfloat16* __restrict__ Olo,
    int N, int K, int act)
{
    extern __shared__ __align__(128) char smem[];
    const uint32_t sbase = smem_u32(smem);
    const int tid = threadIdx.x;
    const int lane = tid & 31, wid = tid >> 5;
    const int warp_m = wid & 3, warp_n = wid >> 2;
    const int m0 = blockIdx.y * 128, n0 = blockIdx.x * 128;

    float acc[2][8][4];
    #pragma unroll
    for (int t = 0; t < 2; t++)
        #pragma unroll
        for (int j = 0; j < 8; j++)
            #pragma unroll
            for (int e = 0; e < 4; e++) acc[t][j][e] = 0.0f;

    int lr0 = tid >> 2,         lc0 = tid & 3;
    int lr1 = (tid + 256) >> 2, lc1 = tid & 3;
    uint32_t lsw0 = lr0 * 64 + ((lc0 ^ ((lr0 >> 1) & 3)) << 4);
    uint32_t lsw1 = lr1 * 64 + ((lc1 ^ ((lr1 >> 1) & 3)) << 4);

    auto stage_load = [&](int ci, int st) {
        const uint32_t sb = sbase + st * G_STAGE;
        const int kk = ci * 32;
        {
            size_t goA = (size_t)(m0 + lr0) * K + kk + lc0 * 8;
            size_t goB = (size_t)(n0 + lr0) * K + kk + lc0 * 8;
            cp_async16(sb + lsw0,         Ahi + goA);
            cp_async16(sb + 8192 + lsw0,  Alo + goA);
            cp_async16(sb + 16384 + lsw0, Bhi + goB);
            cp_async16(sb + 24576 + lsw0, Blo + goB);
        }
        {
            size_t goA = (size_t)(m0 + lr1) * K + kk + lc1 * 8;
            size_t goB = (size_t)(n0 + lr1) * K + kk + lc1 * 8;
            cp_async16(sb + lsw1,         Ahi + goA);
            cp_async16(sb + 8192 + lsw1,  Alo + goA);
            cp_async16(sb + 16384 + lsw1, Bhi + goB);
            cp_async16(sb + 24576 + lsw1, Blo + goB);
        }
        cp_commit();
    };

    const int lrow = lane & 15;
    const int lseg = lane >> 4;
    int arow[2], brow[4];
    #pragma unroll
    for (int t = 0; t < 2; t++) arow[t] = warp_m * 32 + t * 16 + lrow;
    #pragma unroll
    for (int u = 0; u < 4; u++) brow[u] = warp_n * 64 + u * 16 + lrow;

    const int nch = K >> 5;
    stage_load(0, 0);
    stage_load(1, 1);
    stage_load(2, 2);

    for (int i = 0; i < nch; i++) {
        if (i <= nch - 3)      asm volatile("cp.async.wait_group 2;" ::: "memory");
        else if (i == nch - 2) asm volatile("cp.async.wait_group 1;" ::: "memory");
        else                   asm volatile("cp.async.wait_group 0;" ::: "memory");
        __syncthreads();

        const uint32_t sb = sbase + (i & 3) * G_STAGE;
        #pragma unroll
        for (int s = 0; s < 2; s++) {
            const int chunk = 2 * s + lseg;
            uint32_t ah[2][4], al[2][4], bh[4][4], bl[4][4];
            #pragma unroll
            for (int t = 0; t < 2; t++) {
                uint32_t a = sb + arow[t] * 64 + ((chunk ^ ((arow[t] >> 1) & 3)) << 4);
                ldsm_x4(ah[t], a);
                ldsm_x4(al[t], a + 8192);
            }
            #pragma unroll
            for (int u = 0; u < 4; u++) {
                uint32_t a = sb + 16384 + brow[u] * 64 + ((chunk ^ ((brow[u] >> 1) & 3)) << 4);
                ldsm_x4(bh[u], a);
                ldsm_x4(bl[u], a + 8192);
            }
            #pragma unroll
            for (int t = 0; t < 2; t++)
                #pragma unroll
                for (int u = 0; u < 4; u++) {
                    mma16816(acc[t][2 * u],     ah[t], bh[u][0], bh[u][2]);
                    mma16816(acc[t][2 * u + 1], ah[t], bh[u][1], bh[u][3]);
                    mma16816(acc[t][2 * u],     ah[t], bl[u][0], bl[u][2]);
                    mma16816(acc[t][2 * u + 1], ah[t], bl[u][1], bl[u][3]);
                    mma16816(acc[t][2 * u],     al[t], bh[u][0], bh[u][2]);
                    mma16816(acc[t][2 * u + 1], al[t], bh[u][1], bh[u][3]);
                }
        }
        __syncthreads();
        if (i + 3 < nch) stage_load(i + 3, (i + 3) & 3);
    }

    #pragma unroll
    for (int t = 0; t < 2; t++) {
        const int rbase = m0 + warp_m * 32 + t * 16 + (lane >> 2);
        #pragma unroll
        for (int j = 0; j < 8; j++) {
            const int col = n0 + warp_n * 64 + j * 8 + 2 * (lane & 3);
            const float b0 = __ldg(bias + col), b1 = __ldg(bias + col + 1);
            #pragma unroll
            for (int half = 0; half < 2; half++) {
                const int row = rbase + 8 * half;
                float v0 = acc[t][j][2 * half]     + b0;
                float v1 = acc[t][j][2 * half + 1] + b1;
                if (act) {
                    v0 = 0.5f * v0 * (1.0f + erff(v0 * 0.70710678118654752f));
                    v1 = 0.5f * v1 * (1.0f + erff(v1 * 0.70710678118654752f));
                }
                const size_t off = (size_t)row * N + col;
                if (Cf) {
                    *(float2*)(Cf + off) = make_float2(v0, v1);
                } else {
                    __nv_bfloat16 h0 = __float2bfloat16(v0);
                    __nv_bfloat16 h1 = __float2bfloat16(v1);
                    __nv_bfloat16 l0 = __float2bfloat16(v0 - __bfloat162float(h0));
                    __nv_bfloat16 l1 = __float2bfloat16(v1 - __bfloat162float(h1));
                    *(uint32_t*)(Ohi + off) =
                        (uint32_t)__bfloat16_as_ushort(h0) | ((uint32_t)__bfloat16_as_ushort(h1) << 16);
                    *(uint32_t*)(Olo + off) =
                        (uint32_t)__bfloat16_as_ushort(l0) | ((uint32_t)__bfloat16_as_ushort(l1) << 16);
                }
            }
        }
    }
}

// ---------------- Bias precompute ----------------
__global__ void bias_kernel(const int* __restrict__ beats, float* __restrict__ out) {
    __shared__ int sb[NBEATS];
    int i = blockIdx.x;
    int j = threadIdx.x;
    if (threadIdx.x < NBEATS) sb[threadIdx.x] = beats[threadIdx.x];
    __syncthreads();
    float bb = 0.0f;
    #pragma unroll 8
    for (int n = 0; n < NBEATS; n++) {
        int bf = sb[n];
        if (j == bf) bb = fmaxf(bb, 2.0f);
        if (bf > 0      && j == bf - 1) bb = fmaxf(bb, 1.0f);
        if (bf < TA - 1 && j == bf + 1) bb = fmaxf(bb, 1.0f);
    }
    float scale = (float)(TA - 1) / (float)(TM - 1);
    float d = (float)i * scale - (float)j;
    out[i * TA + j] = -(d * d) * (1.0f / 32.0f) + bb;
}

// ---------------- Attention (SIMT) ----------------
#define QS(r, c) Qs[(r) * 65 + (c)]
#define KS(r, c) Ks[(r) * 65 + (c)]
#define SS(r, c) Ss[(r) * 513 + (c)]
#define ATTN_SMEM ((2 * 64 * 65 + 64 * 513) * 4)

__global__ __launch_bounds__(256) void attn_kernel(
    const float* __restrict__ Qb, int ldq, int qbase,
    const float* __restrict__ Kb, int ldk, int kbase,
    const float* __restrict__ Vb, int ldv, int vbase,
    float* __restrict__ Out, const float* __restrict__ bias, float scale)
{
    extern __shared__ float sm[];
    float* Qs = sm;
    float* Ks = sm + 64 * 65;
    float* Ss = sm + 2 * 64 * 65;

    int tid = threadIdx.x;
    int qt = blockIdx.x;
    int bh = blockIdx.y;
    int b = bh & (BATCH - 1);
    int h = bh >> 5;
    int tx = tid & 15, ty = tid >> 4;

    for (int p = tid; p < 64 * 16; p += 256) {
        int r = p >> 4, c = (p & 15) << 2;
        float4 v = *(const float4*)(Qb + (size_t)((qt * 64 + r) * BATCH + b) * ldq + qbase + h * HDIM + c);
        QS(r, c) = v.x; QS(r, c + 1) = v.y; QS(r, c + 2) = v.z; QS(r, c + 3) = v.w;
    }

    for (int kt = 0; kt < 8; kt++) {
        __syncthreads();
        for (int p = tid; p < 64 * 16; p += 256) {
            int r = p >> 4, c = (p & 15) << 2;
            float4 v = *(const float4*)(Kb + (size_t)((kt * 64 + r) * BATCH + b) * ldk + kbase + h * HDIM + c);
            KS(r, c) = v.x; KS(r, c + 1) = v.y; KS(r, c + 2) = v.z; KS(r, c + 3) = v.w;
        }
        __syncthreads();
        float s[4][4];
        #pragma unroll
        for (int i = 0; i < 4; i++)
            #pragma unroll
            for (int j = 0; j < 4; j++) s[i][j] = 0.0f;
        #pragma unroll 8
        for (int kk = 0; kk < 64; kk++) {
            float qr[4], kr[4];
            #pragma unroll
            for (int i = 0; i < 4; i++) qr[i] = QS(ty * 4 + i, kk);
            #pragma unroll
            for (int j = 0; j < 4; j++) kr[j] = KS(tx * 4 + j, kk);
            #pragma unroll
            for (int i = 0; i < 4; i++)
                #pragma unroll
                for (int j = 0; j < 4; j++) s[i][j] += qr[i] * kr[j];
        }
        #pragma unroll
        for (int i = 0; i < 4; i++) {
            int qg = qt * 64 + ty * 4 + i;
            #pragma unroll
            for (int j = 0; j < 4; j++) {
                int kg = kt * 64 + tx * 4 + j;
                float v = s[i][j] * scale;
                if (bias) v += bias[qg * TA + kg];
                SS(ty * 4 + i, kg) = v;
            }
        }
    }
    __syncthreads();

    int w = tid >> 5, lane = tid & 31;
    for (int r = w; r < 64; r += 8) {
        float m = -1e30f;
        for (int c = lane; c < 512; c += 32) m = fmaxf(m, SS(r, c));
        #pragma unroll
        for (int o = 16; o > 0; o >>= 1) m = fmaxf(m, __shfl_xor_sync(0xffffffffu, m, o));
        float sum = 0.0f;
        for (int c = lane; c < 512; c += 32) {
            float e = expf(SS(r, c) - m);
            SS(r, c) = e;
            sum += e;
        }
        #pragma unroll
        for (int o = 16; o > 0; o >>= 1) sum += __shfl_xor_sync(0xffffffffu, sum, o);
        float inv = 1.0f / sum;
        for (int c = lane; c < 512; c += 32) SS(r, c) *= inv;
    }

    float acc[4][4];
    #pragma unroll
    for (int i = 0; i < 4; i++)
        #pragma unroll
        for (int j = 0; j < 4; j++) acc[i][j] = 0.0f;

    for (int vt = 0; vt < 8; vt++) {
        __syncthreads();
        for (int p = tid; p < 64 * 16; p += 256) {
            int r = p >> 4, c = (p & 15) << 2;
            float4 v = *(const float4*)(Vb + (size_t)((vt * 64 + r) * BATCH + b) * ldv + vbase + h * HDIM + c);
            KS(r, c) = v.x; KS(r, c + 1) = v.y; KS(r, c + 2) = v.z; KS(r, c + 3) = v.w;
        }
        __syncthreads();
        #pragma unroll 8
        for (int kk = 0; kk < 64; kk++) {
            float pr[4], vr[4];
            #pragma unroll
            for (int i = 0; i < 4; i++) pr[i] = SS(ty * 4 + i, vt * 64 + kk);
            #pragma unroll
            for (int j = 0; j < 4; j++) vr[j] = KS(kk, tx * 4 + j);
            #pragma unroll
            for (int i = 0; i < 4; i++)
                #pragma unroll
                for (int j = 0; j < 4; j++) acc[i][j] += pr[i] * vr[j];
        }
    }
    #pragma unroll
    for (int i = 0; i < 4; i++) {
        int qg = qt * 64 + ty * 4 + i;
        #pragma unroll
        for (int j = 0; j < 4; j++)
            Out[(size_t)(qg * BATCH + b) * D_MODEL + h * HDIM + tx * 4 + j] = acc[i][j];
    }
}

// ---------------- Fused residual + LayerNorm ----------------
__global__ __launch_bounds__(256) void add_ln_kernel(
    const float* __restrict__ A, const float* __restrict__ Bv,
    const float* __restrict__ gatePtr,
    const float* __restrict__ gamma, const float* __restrict__ beta,
    float* __restrict__ out)
{
    int t = blockIdx.x;
    int tid = threadIdx.x;
    float gscale = gatePtr ? tanhf(*gatePtr) : 1.0f;
    const float4* a4 = (const float4*)(A  + (size_t)t * D_MODEL);
    const float4* b4 = (const float4*)(Bv + (size_t)t * D_MODEL);
    float4 av = a4[tid], bv = b4[tid];
    float x0 = av.x + gscale * bv.x;
    float x1 = av.y + gscale * bv.y;
    float x2 = av.z + gscale * bv.z;
    float x3 = av.w + gscale * bv.w;
    float s  = x0 + x1 + x2 + x3;
    float ss = x0 * x0 + x1 * x1 + x2 * x2 + x3 * x3;

    __shared__ float rs[8], rss[8];
    #pragma unroll
    for (int o = 16; o > 0; o >>= 1) {
        s  += __shfl_xor_sync(0xffffffffu, s,  o);
        ss += __shfl_xor_sync(0xffffffffu, ss, o);
    }
    if ((tid & 31) == 0) { rs[tid >> 5] = s; rss[tid >> 5] = ss; }
    __syncthreads();
    float stot = 0.0f, sstot = 0.0f;
    #pragma unroll
    for (int i = 0; i < 8; i++) { stot += rs[i]; sstot += rss[i]; }
    float mean = stot * (1.0f / D_MODEL);
    float var  = sstot * (1.0f / D_MODEL) - mean * mean;
    float rstd = rsqrtf(var + LN_EPS);

    const float4* g4 = (const float4*)gamma;
    const float4* be4 = (const float4*)beta;
    float4 g = g4[tid], be = be4[tid];
    float4 o;
    o.x = (x0 - mean) * rstd * g.x + be.x;
    o.y = (x1 - mean) * rstd * g.y + be.y;
    o.z = (x2 - mean) * rstd * g.z + be.z;
    o.w = (x3 - mean) * rstd * g.w + be.w;
    ((float4*)(out + (size_t)t * D_MODEL))[tid] = o;
}

// ---------------- Launch ----------------
extern "C" void kernel_launch(void* const* d_in, const int* in_sizes, int n_in,
                              void* d_out, int out_size) {
    const float* src      = (const float*)d_in[0];
    const float* audio    = (const float*)d_in[1];
    const int*   beats    = (const int*)  d_in[2];
    const float* sa_in_w  = (const float*)d_in[3];
    const float* sa_in_b  = (const float*)d_in[4];
    const float* sa_out_w = (const float*)d_in[5];
    const float* sa_out_b = (const float*)d_in[6];
    const float* ca_in_w  = (const float*)d_in[7];
    const float* ca_in_b  = (const float*)d_in[8];
    const float* ca_out_w = (const float*)d_in[9];
    const float* ca_out_b = (const float*)d_in[10];
    const float* gate     = (const float*)d_in[11];
    const float* n1_g     = (const float*)d_in[12];
    const float* n1_b     = (const float*)d_in[13];
    const float* nc_g     = (const float*)d_in[14];
    const float* nc_b     = (const float*)d_in[15];
    const float* n2_g     = (const float*)d_in[16];
    const float* n2_b     = (const float*)d_in[17];
    const float* lin1_w   = (const float*)d_in[18];
    const float* lin1_b   = (const float*)d_in[19];
    const float* lin2_w   = (const float*)d_in[20];
    const float* lin2_b   = (const float*)d_in[21];
    float* out = (float*)d_out;

    float *qkv, *attn, *tmp, *x1, *q, *kv, *x2, *ff2, *bias;
    __nv_bfloat16 *Xhi, *Xlo, *Hhi, *Hlo, *Whi, *Wlo;
    cudaGetSymbolAddress((void**)&qkv,  g_qkv);
    cudaGetSymbolAddress((void**)&attn, g_attn);
    cudaGetSymbolAddress((void**)&tmp,  g_tmp);
    cudaGetSymbolAddress((void**)&x1,   g_x1);
    cudaGetSymbolAddress((void**)&q,    g_q);
    cudaGetSymbolAddress((void**)&kv,   g_kv);
    cudaGetSymbolAddress((void**)&x2,   g_x2);
    cudaGetSymbolAddress((void**)&ff2,  g_ff2);
    cudaGetSymbolAddress((void**)&bias, g_bias);
    cudaGetSymbolAddress((void**)&Xhi,  g_Xhi);
    cudaGetSymbolAddress((void**)&Xlo,  g_Xlo);
    cudaGetSymbolAddress((void**)&Hhi,  g_Hhi);
    cudaGetSymbolAddress((void**)&Hlo,  g_Hlo);
    cudaGetSymbolAddress((void**)&Whi,  g_Whi);
    cudaGetSymbolAddress((void**)&Wlo,  g_Wlo);

    cudaFuncSetAttribute(attn_kernel, cudaFuncAttributeMaxDynamicSharedMemorySize, ATTN_SMEM);
    cudaFuncSetAttribute(gemm_mma, cudaFuncAttributeMaxDynamicSharedMemorySize, G_SMEM);

    const int CVT_B = 256 * 4;
    #define CVT(srcp, hip, lop, n) cvt_kernel<<<(n) / CVT_B, 256>>>(srcp, hip, lop, n)
    #define GEMM(ahi, alo, bhi, blo, bp, cf, ohi, olo, Nn, Kk, act) \
        gemm_mma<<<dim3((Nn) / 128, NTOK / 128), 256, G_SMEM>>>(ahi, alo, bhi, blo, bp, cf, ohi, olo, Nn, Kk, act)

    bias_kernel<<<TM, TA>>>(beats, bias);
    CVT(sa_in_w,  Whi + W_SAIN,  Wlo + W_SAIN,  3 * D_MODEL * D_MODEL);
    CVT(sa_out_w, Whi + W_SAOUT, Wlo + W_SAOUT, D_MODEL * D_MODEL);
    CVT(ca_in_w,  Whi + W_CAIN,  Wlo + W_CAIN,  3 * D_MODEL * D_MODEL);
    CVT(ca_out_w, Whi + W_CAOUT, Wlo + W_CAOUT, D_MODEL * D_MODEL);
    CVT(lin1_w,   Whi + W_LIN1,  Wlo + W_LIN1,  DFF * D_MODEL);
    CVT(lin2_w,   Whi + W_LIN2,  Wlo + W_LIN2,  D_MODEL * DFF);

    // 1) SA packed QKV
    CVT(src, Xhi, Xlo, NTOK * D_MODEL);
    GEMM(Xhi, Xlo, Whi + W_SAIN, Wlo + W_SAIN, sa_in_b, qkv,
         (__nv_bfloat16*)nullptr, (__nv_bfloat16*)nullptr, 3 * D_MODEL, D_MODEL, 0);

    // 2) SA attention
    attn_kernel<<<dim3(TM / 64, BATCH * NHEAD), 256, ATTN_SMEM>>>(
        qkv, 3 * D_MODEL, 0, qkv, 3 * D_MODEL, D_MODEL, qkv, 3 * D_MODEL, 2 * D_MODEL,
        attn, nullptr, 0.125f);

    // 3) SA out-proj
    CVT(attn, Xhi, Xlo, NTOK * D_MODEL);
    GEMM(Xhi, Xlo, Whi + W_SAOUT, Wlo + W_SAOUT, sa_out_b, tmp,
         (__nv_bfloat16*)nullptr, (__nv_bfloat16*)nullptr, D_MODEL, D_MODEL, 0);

    // 4) x1 = LN1(src + sa)
    add_ln_kernel<<<NTOK, 256>>>(src, tmp, nullptr, n1_g, n1_b, x1);

    // 5) CA projections
    CVT(x1, Xhi, Xlo, NTOK * D_MODEL);
    GEMM(Xhi, Xlo, Whi + W_CAIN, Wlo + W_CAIN, ca_in_b, q,
         (__nv_bfloat16*)nullptr, (__nv_bfloat16*)nullptr, D_MODEL, D_MODEL, 0);
    CVT(audio, Xhi, Xlo, NTOK * D_MODEL);
    GEMM(Xhi, Xlo, Whi + W_CAIN + (size_t)D_MODEL * D_MODEL, Wlo + W_CAIN + (size_t)D_MODEL * D_MODEL,
         ca_in_b + D_MODEL, kv, (__nv_bfloat16*)nullptr, (__nv_bfloat16*)nullptr,
         2 * D_MODEL, D_MODEL, 0);

    // 6) CA attention (biased)
    attn_kernel<<<dim3(TM / 64, BATCH * NHEAD), 256, ATTN_SMEM>>>(
        q, D_MODEL, 0, kv, 2 * D_MODEL, 0, kv, 2 * D_MODEL, D_MODEL,
        attn, bias, 0.125f);

    // 7) CA out-proj
    CVT(attn, Xhi, Xlo, NTOK * D_MODEL);
    GEMM(Xhi, Xlo, Whi + W_CAOUT, Wlo + W_CAOUT, ca_out_b, tmp,
         (__nv_bfloat16*)nullptr, (__nv_bfloat16*)nullptr, D_MODEL, D_MODEL, 0);

    // 8) x2 = LNc(x1 + tanh(gate)*cross)
    add_ln_kernel<<<NTOK, 256>>>(x1, tmp, gate, nc_g, nc_b, x2);

    // 9) FFN
    CVT(x2, Xhi, Xlo, NTOK * D_MODEL);
    GEMM(Xhi, Xlo, Whi + W_LIN1, Wlo + W_LIN1, lin1_b, (float*)nullptr, Hhi, Hlo,
         DFF, D_MODEL, 1);
    GEMM(Hhi, Hlo, Whi + W_LIN2, Wlo + W_LIN2, lin2_b, ff2,
         (__nv_bfloat16*)nullptr, (__nv_bfloat16*)nullptr, D_MODEL, DFF, 0);

    // 10) out = LN2(x2 + ff)
    add_ln_kernel<<<NTOK, 256>>>(x2, ff2, nullptr, n2_g, n2_b, out);
}

// round 5
// speedup vs baseline: 2.6811x; 1.5632x over previous
#include <cuda_runtime.h>
#include <cuda_bf16.h>
#include <math.h>
#include <stdint.h>

// ---------------- Problem constants ----------------
#define D_MODEL 1024
#define NHEAD   16
#define HDIM    64
#define DFF     4096
#define TM      512
#define TA      512
#define BATCH   32
#define NTOK    (TM * BATCH)   // 16384
#define NBEATS  64
#define LN_EPS  1e-5f

// ---------------- fp32 scratch ----------------
__device__ float g_tmp [NTOK * D_MODEL];
__device__ float g_x1  [NTOK * D_MODEL];
__device__ float g_x2  [NTOK * D_MODEL];
__device__ float g_ff2 [NTOK * D_MODEL];
__device__ float g_bias[TM * TA];

// ---------------- bf16 split scratch ----------------
__device__ __nv_bfloat16 g_Xhi [NTOK * D_MODEL];
__device__ __nv_bfloat16 g_Xlo [NTOK * D_MODEL];
__device__ __nv_bfloat16 g_Hhi [NTOK * DFF];
__device__ __nv_bfloat16 g_Hlo [NTOK * DFF];
__device__ __nv_bfloat16 g_QKVhi[NTOK * 3 * D_MODEL];
__device__ __nv_bfloat16 g_QKVlo[NTOK * 3 * D_MODEL];
__device__ __nv_bfloat16 g_KVhi[NTOK * 2 * D_MODEL];
__device__ __nv_bfloat16 g_KVlo[NTOK * 2 * D_MODEL];
__device__ __nv_bfloat16 g_CQhi[NTOK * D_MODEL];
__device__ __nv_bfloat16 g_CQlo[NTOK * D_MODEL];
__device__ __nv_bfloat16 g_Whi[16777216];
__device__ __nv_bfloat16 g_Wlo[16777216];

#define W_SAIN   0u
#define W_SAOUT  3145728u
#define W_CAIN   4194304u
#define W_CAOUT  7340032u
#define W_LIN1   8388608u
#define W_LIN2  12582912u

// ================= helpers (non-'a' PTX only) =================
__device__ __forceinline__ uint32_t smem_u32(const void* p) {
    uint32_t a;
    asm("{ .reg .u64 t; cvta.to.shared.u64 t, %1; cvt.u32.u64 %0, t; }" : "=r"(a) : "l"(p));
    return a;
}
__device__ __forceinline__ void cp_async16(uint32_t saddr, const void* g) {
    asm volatile("cp.async.cg.shared.global [%0], [%1], 16;" :: "r"(saddr), "l"(g));
}
__device__ __forceinline__ void cp_commit() {
    asm volatile("cp.async.commit_group;" ::: "memory");
}
__device__ __forceinline__ void ldsm_x4(uint32_t (&r)[4], uint32_t addr) {
    asm volatile("ldmatrix.sync.aligned.m8n8.x4.shared.b16 {%0,%1,%2,%3}, [%4];"
                 : "=r"(r[0]), "=r"(r[1]), "=r"(r[2]), "=r"(r[3]) : "r"(addr));
}
__device__ __forceinline__ void ldsm_x4_t(uint32_t (&r)[4], uint32_t addr) {
    asm volatile("ldmatrix.sync.aligned.m8n8.x4.trans.shared.b16 {%0,%1,%2,%3}, [%4];"
                 : "=r"(r[0]), "=r"(r[1]), "=r"(r[2]), "=r"(r[3]) : "r"(addr));
}
__device__ __forceinline__ void mma16816(float (&d)[4], const uint32_t (&a)[4],
                                         uint32_t b0, uint32_t b1) {
    asm volatile(
        "mma.sync.aligned.m16n8k16.row.col.f32.bf16.bf16.f32 "
        "{%0,%1,%2,%3}, {%4,%5,%6,%7}, {%8,%9}, {%0,%1,%2,%3};"
        : "+f"(d[0]), "+f"(d[1]), "+f"(d[2]), "+f"(d[3])
        : "r"(a[0]), "r"(a[1]), "r"(a[2]), "r"(a[3]), "r"(b0), "r"(b1));
}
__device__ __forceinline__ uint32_t pack_bf16x2(float x, float y) {
    return (uint32_t)__bfloat16_as_ushort(__float2bfloat16(x)) |
           ((uint32_t)__bfloat16_as_ushort(__float2bfloat16(y)) << 16);
}

// ================= split-bf16 convert =================
__global__ __launch_bounds__(256) void cvt_kernel(
    const float* __restrict__ src, __nv_bfloat16* __restrict__ hi,
    __nv_bfloat16* __restrict__ lo, int n)
{
    int i = (blockIdx.x * 256 + threadIdx.x) * 4;
    if (i >= n) return;
    float4 v = *(const float4*)(src + i);
    __nv_bfloat16 h0 = __float2bfloat16(v.x), h1 = __float2bfloat16(v.y);
    __nv_bfloat16 h2 = __float2bfloat16(v.z), h3 = __float2bfloat16(v.w);
    uint2 uh, ul;
    uh.x = (uint32_t)__bfloat16_as_ushort(h0) | ((uint32_t)__bfloat16_as_ushort(h1) << 16);
    uh.y = (uint32_t)__bfloat16_as_ushort(h2) | ((uint32_t)__bfloat16_as_ushort(h3) << 16);
    ul.x = pack_bf16x2(v.x - __bfloat162float(h0), v.y - __bfloat162float(h1));
    ul.y = pack_bf16x2(v.z - __bfloat162float(h2), v.w - __bfloat162float(h3));
    *(uint2*)(hi + i) = uh;
    *(uint2*)(lo + i) = ul;
}

// ================= mma.sync GEMM =================
// C[M,N] = A[M,K]*B[N,K]^T + bias, 3-term split-bf16. CTA 128x128, BK=32, 4 stages.
#define G_STAGE 32768
#define G_SMEM  (4 * G_STAGE)

__global__ __launch_bounds__(256, 1) void gemm_mma(
    const __nv_bfloat16* __restrict__ Ahi, const __nv_bfloat16* __restrict__ Alo,
    const __nv_bfloat16* __restrict__ Bhi, const __nv_bfloat16* __restrict__ Blo,
    const float* __restrict__ bias, float* __restrict__ Cf,
    __nv_bfloat16* __restrict__ Ohi, __nv_bfloat16* __restrict__ Olo,
    int N, int K, int act)
{
    extern __shared__ __align__(128) char smem[];
    const uint32_t sbase = smem_u32(smem);
    const int tid = threadIdx.x;
    const int lane = tid & 31, wid = tid >> 5;
    const int warp_m = wid & 3, warp_n = wid >> 2;
    const int m0 = blockIdx.y * 128, n0 = blockIdx.x * 128;

    float acc[2][8][4];
    #pragma unroll
    for (int t = 0; t < 2; t++)
        #pragma unroll
        for (int j = 0; j < 8; j++)
            #pragma unroll
            for (int e = 0; e < 4; e++) acc[t][j][e] = 0.0f;

    int lr0 = tid >> 2,         lc0 = tid & 3;
    int lr1 = (tid + 256) >> 2, lc1 = tid & 3;
    uint32_t lsw0 = lr0 * 64 + ((lc0 ^ ((lr0 >> 1) & 3)) << 4);
    uint32_t lsw1 = lr1 * 64 + ((lc1 ^ ((lr1 >> 1) & 3)) << 4);

    auto stage_load = [&](int ci, int st) {
        const uint32_t sb = sbase + st * G_STAGE;
        const int kk = ci * 32;
        {
            size_t goA = (size_t)(m0 + lr0) * K + kk + lc0 * 8;
            size_t goB = (size_t)(n0 + lr0) * K + kk + lc0 * 8;
            cp_async16(sb + lsw0,         Ahi + goA);
            cp_async16(sb + 8192 + lsw0,  Alo + goA);
            cp_async16(sb + 16384 + lsw0, Bhi + goB);
            cp_async16(sb + 24576 + lsw0, Blo + goB);
        }
        {
            size_t goA = (size_t)(m0 + lr1) * K + kk + lc1 * 8;
            size_t goB = (size_t)(n0 + lr1) * K + kk + lc1 * 8;
            cp_async16(sb + lsw1,         Ahi + goA);
            cp_async16(sb + 8192 + lsw1,  Alo + goA);
            cp_async16(sb + 16384 + lsw1, Bhi + goB);
            cp_async16(sb + 24576 + lsw1, Blo + goB);
        }
        cp_commit();
    };

    const int lrow = lane & 15;
    const int lseg = lane >> 4;
    int arow[2], brow[4];
    #pragma unroll
    for (int t = 0; t < 2; t++) arow[t] = warp_m * 32 + t * 16 + lrow;
    #pragma unroll
    for (int u = 0; u < 4; u++) brow[u] = warp_n * 64 + u * 16 + lrow;

    const int nch = K >> 5;
    stage_load(0, 0);
    stage_load(1, 1);
    stage_load(2, 2);

    for (int i = 0; i < nch; i++) {
        if (i <= nch - 3)      asm volatile("cp.async.wait_group 2;" ::: "memory");
        else if (i == nch - 2) asm volatile("cp.async.wait_group 1;" ::: "memory");
        else                   asm volatile("cp.async.wait_group 0;" ::: "memory");
        __syncthreads();
        if (i + 3 < nch) stage_load(i + 3, (i + 3) & 3);   // writes stage consumed at i-1

        const uint32_t sb = sbase + (i & 3) * G_STAGE;
        #pragma unroll
        for (int s = 0; s < 2; s++) {
            const int chunk = 2 * s + lseg;
            uint32_t ah[2][4], al[2][4], bh[4][4], bl[4][4];
            #pragma unroll
            for (int t = 0; t < 2; t++) {
                uint32_t a = sb + arow[t] * 64 + ((chunk ^ ((arow[t] >> 1) & 3)) << 4);
                ldsm_x4(ah[t], a);
                ldsm_x4(al[t], a + 8192);
            }
            #pragma unroll
            for (int u = 0; u < 4; u++) {
                uint32_t a = sb + 16384 + brow[u] * 64 + ((chunk ^ ((brow[u] >> 1) & 3)) << 4);
                ldsm_x4(bh[u], a);
                ldsm_x4(bl[u], a + 8192);
            }
            #pragma unroll
            for (int t = 0; t < 2; t++)
                #pragma unroll
                for (int u = 0; u < 4; u++) {
                    mma16816(acc[t][2 * u],     ah[t], bh[u][0], bh[u][2]);
                    mma16816(acc[t][2 * u + 1], ah[t], bh[u][1], bh[u][3]);
                    mma16816(acc[t][2 * u],     ah[t], bl[u][0], bl[u][2]);
                    mma16816(acc[t][2 * u + 1], ah[t], bl[u][1], bl[u][3]);
                    mma16816(acc[t][2 * u],     al[t], bh[u][0], bh[u][2]);
                    mma16816(acc[t][2 * u + 1], al[t], bh[u][1], bh[u][3]);
                }
        }
    }

    #pragma unroll
    for (int t = 0; t < 2; t++) {
        const int rbase = m0 + warp_m * 32 + t * 16 + (lane >> 2);
        #pragma unroll
        for (int j = 0; j < 8; j++) {
            const int col = n0 + warp_n * 64 + j * 8 + 2 * (lane & 3);
            const float b0 = __ldg(bias + col), b1 = __ldg(bias + col + 1);
            #pragma unroll
            for (int half = 0; half < 2; half++) {
                const int row = rbase + 8 * half;
                float v0 = acc[t][j][2 * half]     + b0;
                float v1 = acc[t][j][2 * half + 1] + b1;
                if (act) {
                    v0 = 0.5f * v0 * (1.0f + erff(v0 * 0.70710678118654752f));
                    v1 = 0.5f * v1 * (1.0f + erff(v1 * 0.70710678118654752f));
                }
                const size_t off = (size_t)row * N + col;
                if (Cf) {
                    *(float2*)(Cf + off) = make_float2(v0, v1);
                } else {
                    __nv_bfloat16 h0 = __float2bfloat16(v0);
                    __nv_bfloat16 h1 = __float2bfloat16(v1);
                    *(uint32_t*)(Ohi + off) =
                        (uint32_t)__bfloat16_as_ushort(h0) | ((uint32_t)__bfloat16_as_ushort(h1) << 16);
                    *(uint32_t*)(Olo + off) =
                        pack_bf16x2(v0 - __bfloat162float(h0), v1 - __bfloat162float(h1));
                }
            }
        }
    }
}

// ================= FA2-style attention on mma.sync =================
// grid (TM/64, BATCH*NHEAD), 128 threads (4 warps; warp w owns q-rows w*16..+15).
// K/V tiles of 64 keys stream through 3 smem buffers.
// Buffer layout (32KB): Khi@0, Klo@8K, Vhi@16K, Vlo@24K; rows 128B, 16B chunk c
// of row r stored at r*128 + ((c^(r&7))<<4).
#define AT_BUF  32768
#define AT_SMEM (3 * AT_BUF)

__global__ __launch_bounds__(128) void attn_mma(
    const __nv_bfloat16* __restrict__ Qhi, const __nv_bfloat16* __restrict__ Qlo, int ldq, int qoff,
    const __nv_bfloat16* __restrict__ Khi, const __nv_bfloat16* __restrict__ Klo, int ldk, int koff,
    const __nv_bfloat16* __restrict__ Vhi, const __nv_bfloat16* __restrict__ Vlo, int ldv, int voff,
    __nv_bfloat16* __restrict__ Ohi, __nv_bfloat16* __restrict__ Olo,
    const float* __restrict__ bias, float scale)
{
    extern __shared__ __align__(128) char smem[];
    const uint32_t sbase = smem_u32(smem);
    const int tid = threadIdx.x, lane = tid & 31, w = tid >> 5;
    const int qt = blockIdx.x, bh = blockIdx.y;
    const int b = bh & (BATCH - 1), h = bh >> 5;

    // ---- stage Q (hi/lo) into buffer 0, then ldmatrix into registers
    #pragma unroll
    for (int it = 0; it < 4; it++) {
        int idx = tid + it * 128, r = idx >> 3, c = idx & 7;
        uint32_t sw = r * 128 + ((c ^ (r & 7)) << 4);
        size_t g = (size_t)((qt * 64 + r) * BATCH + b) * ldq + qoff + h * HDIM + c * 8;
        cp_async16(sbase + sw,        Qhi + g);
        cp_async16(sbase + 8192 + sw, Qlo + g);
    }
    cp_commit();
    asm volatile("cp.async.wait_group 0;" ::: "memory");
    __syncthreads();

    const int lr = lane & 15, ls = lane >> 4;
    uint32_t qh[4][4], ql[4][4];
    {
        int qrow = w * 16 + lr;
        #pragma unroll
        for (int kc = 0; kc < 4; kc++) {
            int chunk = 2 * kc + ls;
            uint32_t a = sbase + qrow * 128 + ((chunk ^ (qrow & 7)) << 4);
            ldsm_x4(qh[kc], a);
            ldsm_x4(ql[kc], a + 8192);
        }
    }
    __syncthreads();   // buffer 0 free for K/V now

    auto load_kt = [&](int kt, int st) {
        uint32_t sb = sbase + st * AT_BUF;
        #pragma unroll
        for (int it = 0; it < 4; it++) {
            int idx = tid + it * 128, r = idx >> 3, c = idx & 7;
            uint32_t sw = r * 128 + ((c ^ (r & 7)) << 4);
            size_t rowi = (size_t)((kt * 64 + r) * BATCH + b);
            size_t gk = rowi * ldk + koff + h * HDIM + c * 8;
            size_t gv = rowi * ldv + voff + h * HDIM + c * 8;
            cp_async16(sb + sw,         Khi + gk);
            cp_async16(sb + 8192 + sw,  Klo + gk);
            cp_async16(sb + 16384 + sw, Vhi + gv);
            cp_async16(sb + 24576 + sw, Vlo + gv);
        }
        cp_commit();
    };
    load_kt(0, 0);
    load_kt(1, 1);

    float o[8][4];
    #pragma unroll
    for (int t = 0; t < 8; t++)
        #pragma unroll
        for (int e = 0; e < 4; e++) o[t][e] = 0.0f;
    float mrow0 = -1e30f, mrow1 = -1e30f, lsum0 = 0.0f, lsum1 = 0.0f;

    const int vkbase = ((lane & 16) ? 8 : 0) + (lane & 7);  // key-row within tile for V ldsm.trans
    const int vcsel  = (lane >> 3) & 1;                     // d-chunk half select

    for (int kt = 0; kt < 8; kt++) {
        if (kt < 7) asm volatile("cp.async.wait_group 1;" ::: "memory");
        else        asm volatile("cp.async.wait_group 0;" ::: "memory");
        __syncthreads();
        if (kt + 2 < 8) load_kt(kt + 2, (kt + 2) % 3);
        const uint32_t sb = sbase + (kt % 3) * AT_BUF;

        // ---- S = Q K^T (3-term split)
        float s[8][4];
        #pragma unroll
        for (int t = 0; t < 8; t++)
            #pragma unroll
            for (int e = 0; e < 4; e++) s[t][e] = 0.0f;
        #pragma unroll
        for (int kc = 0; kc < 4; kc++) {
            #pragma unroll
            for (int u = 0; u < 4; u++) {
                int krow = u * 16 + lr, chunk = 2 * kc + ls;
                uint32_t a = sb + krow * 128 + ((chunk ^ (krow & 7)) << 4);
                uint32_t kh[4], kl[4];
                ldsm_x4(kh, a);
                ldsm_x4(kl, a + 8192);
                mma16816(s[2 * u],     qh[kc], kh[0], kh[2]);
                mma16816(s[2 * u + 1], qh[kc], kh[1], kh[3]);
                mma16816(s[2 * u],     qh[kc], kl[0], kl[2]);
                mma16816(s[2 * u + 1], qh[kc], kl[1], kl[3]);
                mma16816(s[2 * u],     ql[kc], kh[0], kh[2]);
                mma16816(s[2 * u + 1], ql[kc], kh[1], kh[3]);
            }
        }

        // ---- scale + bias
        const int row0 = qt * 64 + w * 16 + (lane >> 2);
        if (bias) {
            #pragma unroll
            for (int t = 0; t < 8; t++) {
                int col = kt * 64 + t * 8 + 2 * (lane & 3);
                float2 b0 = *(const float2*)(bias + (size_t)row0 * TA + col);
                float2 b1 = *(const float2*)(bias + (size_t)(row0 + 8) * TA + col);
                s[t][0] = s[t][0] * scale + b0.x; s[t][1] = s[t][1] * scale + b0.y;
                s[t][2] = s[t][2] * scale + b1.x; s[t][3] = s[t][3] * scale + b1.y;
            }
        } else {
            #pragma unroll
            for (int t = 0; t < 8; t++)
                #pragma unroll
                for (int e = 0; e < 4; e++) s[t][e] *= scale;
        }

        // ---- online softmax
        float mx0 = -1e30f, mx1 = -1e30f;
        #pragma unroll
        for (int t = 0; t < 8; t++) {
            mx0 = fmaxf(mx0, fmaxf(s[t][0], s[t][1]));
            mx1 = fmaxf(mx1, fmaxf(s[t][2], s[t][3]));
        }
        mx0 = fmaxf(mx0, __shfl_xor_sync(0xffffffffu, mx0, 1));
        mx0 = fmaxf(mx0, __shfl_xor_sync(0xffffffffu, mx0, 2));
        mx1 = fmaxf(mx1, __shfl_xor_sync(0xffffffffu, mx1, 1));
        mx1 = fmaxf(mx1, __shfl_xor_sync(0xffffffffu, mx1, 2));
        float mn0 = fmaxf(mrow0, mx0), mn1 = fmaxf(mrow1, mx1);
        float a0 = __expf(mrow0 - mn0), a1 = __expf(mrow1 - mn1);
        mrow0 = mn0; mrow1 = mn1;

        float sum0 = 0.0f, sum1 = 0.0f;
        uint32_t phi[4][4], plo[4][4];
        #pragma unroll
        for (int t = 0; t < 8; t++) {
            float p0 = __expf(s[t][0] - mn0), p1 = __expf(s[t][1] - mn0);
            float p2 = __expf(s[t][2] - mn1), p3 = __expf(s[t][3] - mn1);
            sum0 += p0 + p1; sum1 += p2 + p3;
            __nv_bfloat16 h0 = __float2bfloat16(p0), h1 = __float2bfloat16(p1);
            __nv_bfloat16 h2 = __float2bfloat16(p2), h3 = __float2bfloat16(p3);
            const int kc = t >> 1, j = (t & 1) * 2;
            phi[kc][j]     = (uint32_t)__bfloat16_as_ushort(h0) | ((uint32_t)__bfloat16_as_ushort(h1) << 16);
            phi[kc][j + 1] = (uint32_t)__bfloat16_as_ushort(h2) | ((uint32_t)__bfloat16_as_ushort(h3) << 16);
            plo[kc][j]     = pack_bf16x2(p0 - __bfloat162float(h0), p1 - __bfloat162float(h1));
            plo[kc][j + 1] = pack_bf16x2(p2 - __bfloat162float(h2), p3 - __bfloat162float(h3));
        }
        sum0 += __shfl_xor_sync(0xffffffffu, sum0, 1);
        sum0 += __shfl_xor_sync(0xffffffffu, sum0, 2);
        sum1 += __shfl_xor_sync(0xffffffffu, sum1, 1);
        sum1 += __shfl_xor_sync(0xffffffffu, sum1, 2);
        lsum0 = lsum0 * a0 + sum0;
        lsum1 = lsum1 * a1 + sum1;
        #pragma unroll
        for (int t = 0; t < 8; t++) {
            o[t][0] *= a0; o[t][1] *= a0;
            o[t][2] *= a1; o[t][3] *= a1;
        }

        // ---- O += P V (3-term; V via ldmatrix.trans -> n=d, k=key)
        #pragma unroll
        for (int kc = 0; kc < 4; kc++) {
            int vkey = kc * 16 + vkbase;
            #pragma unroll
            for (int du = 0; du < 4; du++) {
                int chunk = 2 * du + vcsel;
                uint32_t a = sb + 16384 + vkey * 128 + ((chunk ^ (vkey & 7)) << 4);
                uint32_t vh[4], vl[4];
                ldsm_x4_t(vh, a);
                ldsm_x4_t(vl, a + 8192);
                mma16816(o[2 * du],     phi[kc], vh[0], vh[2]);
                mma16816(o[2 * du + 1], phi[kc], vh[1], vh[3]);
                mma16816(o[2 * du],     phi[kc], vl[0], vl[2]);
                mma16816(o[2 * du + 1], phi[kc], vl[1], vl[3]);
                mma16816(o[2 * du],     plo[kc], vh[0], vh[2]);
                mma16816(o[2 * du + 1], plo[kc], vh[1], vh[3]);
            }
        }
    }

    // ---- epilogue: O / l, split to bf16 hi/lo
    float inv0 = 1.0f / lsum0, inv1 = 1.0f / lsum1;
    const int row0 = qt * 64 + w * 16 + (lane >> 2);
    #pragma unroll
    for (int t = 0; t < 8; t++) {
        int col = t * 8 + 2 * (lane & 3);
        float v0 = o[t][0] * inv0, v1 = o[t][1] * inv0;
        float v2 = o[t][2] * inv1, v3 = o[t][3] * inv1;
        size_t off0 = (size_t)(row0 * BATCH + b) * D_MODEL + h * HDIM + col;
        size_t off1 = (size_t)((row0 + 8) * BATCH + b) * D_MODEL + h * HDIM + col;
        __nv_bfloat16 h0 = __float2bfloat16(v0), h1 = __float2bfloat16(v1);
        __nv_bfloat16 h2 = __float2bfloat16(v2), h3 = __float2bfloat16(v3);
        *(uint32_t*)(Ohi + off0) = (uint32_t)__bfloat16_as_ushort(h0) | ((uint32_t)__bfloat16_as_ushort(h1) << 16);
        *(uint32_t*)(Olo + off0) = pack_bf16x2(v0 - __bfloat162float(h0), v1 - __bfloat162float(h1));
        *(uint32_t*)(Ohi + off1) = (uint32_t)__bfloat16_as_ushort(h2) | ((uint32_t)__bfloat16_as_ushort(h3) << 16);
        *(uint32_t*)(Olo + off1) = pack_bf16x2(v2 - __bfloat162float(h2), v3 - __bfloat162float(h3));
    }
}

// ---------------- Bias precompute ----------------
__global__ void bias_kernel(const int* __restrict__ beats, float* __restrict__ out) {
    __shared__ int sb[NBEATS];
    int i = blockIdx.x;
    int j = threadIdx.x;
    if (threadIdx.x < NBEATS) sb[threadIdx.x] = beats[threadIdx.x];
    __syncthreads();
    float bb = 0.0f;
    #pragma unroll 8
    for (int n = 0; n < NBEATS; n++) {
        int bf = sb[n];
        if (j == bf) bb = fmaxf(bb, 2.0f);
        if (bf > 0      && j == bf - 1) bb = fmaxf(bb, 1.0f);
        if (bf < TA - 1 && j == bf + 1) bb = fmaxf(bb, 1.0f);
    }
    float scale = (float)(TA - 1) / (float)(TM - 1);
    float d = (float)i * scale - (float)j;
    out[i * TA + j] = -(d * d) * (1.0f / 32.0f) + bb;
}

// ---------------- Fused residual + LayerNorm ----------------
__global__ __launch_bounds__(256) void add_ln_kernel(
    const float* __restrict__ A, const float* __restrict__ Bv,
    const float* __restrict__ gatePtr,
    const float* __restrict__ gamma, const float* __restrict__ beta,
    float* __restrict__ out)
{
    int t = blockIdx.x;
    int tid = threadIdx.x;
    float gscale = gatePtr ? tanhf(*gatePtr) : 1.0f;
    const float4* a4 = (const float4*)(A  + (size_t)t * D_MODEL);
    const float4* b4 = (const float4*)(Bv + (size_t)t * D_MODEL);
    float4 av = a4[tid], bv = b4[tid];
    float x0 = av.x + gscale * bv.x;
    float x1 = av.y + gscale * bv.y;
    float x2 = av.z + gscale * bv.z;
    float x3 = av.w + gscale * bv.w;
    float s  = x0 + x1 + x2 + x3;
    float ss = x0 * x0 + x1 * x1 + x2 * x2 + x3 * x3;

    __shared__ float rs[8], rss[8];
    #pragma unroll
    for (int o = 16; o > 0; o >>= 1) {
        s  += __shfl_xor_sync(0xffffffffu, s,  o);
        ss += __shfl_xor_sync(0xffffffffu, ss, o);
    }
    if ((tid & 31) == 0) { rs[tid >> 5] = s; rss[tid >> 5] = ss; }
    __syncthreads();
    float stot = 0.0f, sstot = 0.0f;
    #pragma unroll
    for (int i = 0; i < 8; i++) { stot += rs[i]; sstot += rss[i]; }
    float mean = stot * (1.0f / D_MODEL);
    float var  = sstot * (1.0f / D_MODEL) - mean * mean;
    float rstd = rsqrtf(var + LN_EPS);

    const float4* g4 = (const float4*)gamma;
    const float4* be4 = (const float4*)beta;
    float4 g = g4[tid], be = be4[tid];
    float4 o;
    o.x = (x0 - mean) * rstd * g.x + be.x;
    o.y = (x1 - mean) * rstd * g.y + be.y;
    o.z = (x2 - mean) * rstd * g.z + be.z;
    o.w = (x3 - mean) * rstd * g.w + be.w;
    ((float4*)(out + (size_t)t * D_MODEL))[tid] = o;
}

// ---------------- Launch ----------------
extern "C" void kernel_launch(void* const* d_in, const int* in_sizes, int n_in,
                              void* d_out, int out_size) {
    const float* src      = (const float*)d_in[0];
    const float* audio    = (const float*)d_in[1];
    const int*   beats    = (const int*)  d_in[2];
    const float* sa_in_w  = (const float*)d_in[3];
    const float* sa_in_b  = (const float*)d_in[4];
    const float* sa_out_w = (const float*)d_in[5];
    const float* sa_out_b = (const float*)d_in[6];
    const float* ca_in_w  = (const float*)d_in[7];
    const float* ca_in_b  = (const float*)d_in[8];
    const float* ca_out_w = (const float*)d_in[9];
    const float* ca_out_b = (const float*)d_in[10];
    const float* gate     = (const float*)d_in[11];
    const float* n1_g     = (const float*)d_in[12];
    const float* n1_b     = (const float*)d_in[13];
    const float* nc_g     = (const float*)d_in[14];
    const float* nc_b     = (const float*)d_in[15];
    const float* n2_g     = (const float*)d_in[16];
    const float* n2_b     = (const float*)d_in[17];
    const float* lin1_w   = (const float*)d_in[18];
    const float* lin1_b   = (const float*)d_in[19];
    const float* lin2_w   = (const float*)d_in[20];
    const float* lin2_b   = (const float*)d_in[21];
    float* out = (float*)d_out;

    float *tmp, *x1, *x2, *ff2, *bias;
    __nv_bfloat16 *Xhi, *Xlo, *Hhi, *Hlo, *Whi, *Wlo;
    __nv_bfloat16 *QKVhi, *QKVlo, *KVhi, *KVlo, *CQhi, *CQlo;
    cudaGetSymbolAddress((void**)&tmp,  g_tmp);
    cudaGetSymbolAddress((void**)&x1,   g_x1);
    cudaGetSymbolAddress((void**)&x2,   g_x2);
    cudaGetSymbolAddress((void**)&ff2,  g_ff2);
    cudaGetSymbolAddress((void**)&bias, g_bias);
    cudaGetSymbolAddress((void**)&Xhi,  g_Xhi);
    cudaGetSymbolAddress((void**)&Xlo,  g_Xlo);
    cudaGetSymbolAddress((void**)&Hhi,  g_Hhi);
    cudaGetSymbolAddress((void**)&Hlo,  g_Hlo);
    cudaGetSymbolAddress((void**)&Whi,  g_Whi);
    cudaGetSymbolAddress((void**)&Wlo,  g_Wlo);
    cudaGetSymbolAddress((void**)&QKVhi, g_QKVhi);
    cudaGetSymbolAddress((void**)&QKVlo, g_QKVlo);
    cudaGetSymbolAddress((void**)&KVhi,  g_KVhi);
    cudaGetSymbolAddress((void**)&KVlo,  g_KVlo);
    cudaGetSymbolAddress((void**)&CQhi,  g_CQhi);
    cudaGetSymbolAddress((void**)&CQlo,  g_CQlo);

    cudaFuncSetAttribute(gemm_mma, cudaFuncAttributeMaxDynamicSharedMemorySize, G_SMEM);
    cudaFuncSetAttribute(attn_mma, cudaFuncAttributeMaxDynamicSharedMemorySize, AT_SMEM);

    const int CVT_B = 256 * 4;
    #define CVT(srcp, hip, lop, n) cvt_kernel<<<(n) / CVT_B, 256>>>(srcp, hip, lop, n)
    #define GEMM(ahi, alo, bhi, blo, bp, cf, ohi, olo, Nn, Kk, act) \
        gemm_mma<<<dim3((Nn) / 128, NTOK / 128), 256, G_SMEM>>>(ahi, alo, bhi, blo, bp, cf, ohi, olo, Nn, Kk, act)
    #define BF16_NULL (__nv_bfloat16*)nullptr

    bias_kernel<<<TM, TA>>>(beats, bias);
    CVT(sa_in_w,  Whi + W_SAIN,  Wlo + W_SAIN,  3 * D_MODEL * D_MODEL);
    CVT(sa_out_w, Whi + W_SAOUT, Wlo + W_SAOUT, D_MODEL * D_MODEL);
    CVT(ca_in_w,  Whi + W_CAIN,  Wlo + W_CAIN,  3 * D_MODEL * D_MODEL);
    CVT(ca_out_w, Whi + W_CAOUT, Wlo + W_CAOUT, D_MODEL * D_MODEL);
    CVT(lin1_w,   Whi + W_LIN1,  Wlo + W_LIN1,  DFF * D_MODEL);
    CVT(lin2_w,   Whi + W_LIN2,  Wlo + W_LIN2,  D_MODEL * DFF);

    // 1) SA packed QKV (split-bf16 output)
    CVT(src, Xhi, Xlo, NTOK * D_MODEL);
    GEMM(Xhi, Xlo, Whi + W_SAIN, Wlo + W_SAIN, sa_in_b, (float*)nullptr,
         QKVhi, QKVlo, 3 * D_MODEL, D_MODEL, 0);

    // 2) SA attention -> X (split)
    attn_mma<<<dim3(TM / 64, BATCH * NHEAD), 128, AT_SMEM>>>(
        QKVhi, QKVlo, 3 * D_MODEL, 0,
        QKVhi, QKVlo, 3 * D_MODEL, D_MODEL,
        QKVhi, QKVlo, 3 * D_MODEL, 2 * D_MODEL,
        Xhi, Xlo, nullptr, 0.125f);

    // 3) SA out-proj
    GEMM(Xhi, Xlo, Whi + W_SAOUT, Wlo + W_SAOUT, sa_out_b, tmp,
         BF16_NULL, BF16_NULL, D_MODEL, D_MODEL, 0);

    // 4) x1 = LN1(src + sa)
    add_ln_kernel<<<NTOK, 256>>>(src, tmp, nullptr, n1_g, n1_b, x1);

    // 5) CA projections
    CVT(x1, Xhi, Xlo, NTOK * D_MODEL);
    GEMM(Xhi, Xlo, Whi + W_CAIN, Wlo + W_CAIN, ca_in_b, (float*)nullptr,
         CQhi, CQlo, D_MODEL, D_MODEL, 0);
    CVT(audio, Xhi, Xlo, NTOK * D_MODEL);
    GEMM(Xhi, Xlo, Whi + W_CAIN + (size_t)D_MODEL * D_MODEL, Wlo + W_CAIN + (size_t)D_MODEL * D_MODEL,
         ca_in_b + D_MODEL, (float*)nullptr, KVhi, KVlo, 2 * D_MODEL, D_MODEL, 0);

    // 6) CA attention (biased) -> X (split)
    attn_mma<<<dim3(TM / 64, BATCH * NHEAD), 128, AT_SMEM>>>(
        CQhi, CQlo, D_MODEL, 0,
        KVhi, KVlo, 2 * D_MODEL, 0,
        KVhi, KVlo, 2 * D_MODEL, D_MODEL,
        Xhi, Xlo, bias, 0.125f);

    // 7) CA out-proj
    GEMM(Xhi, Xlo, Whi + W_CAOUT, Wlo + W_CAOUT, ca_out_b, tmp,
         BF16_NULL, BF16_NULL, D_MODEL, D_MODEL, 0);

    // 8) x2 = LNc(x1 + tanh(gate)*cross)
    add_ln_kernel<<<NTOK, 256>>>(x1, tmp, gate, nc_g, nc_b, x2);

    // 9) FFN
    CVT(x2, Xhi, Xlo, NTOK * D_MODEL);
    GEMM(Xhi, Xlo, Whi + W_LIN1, Wlo + W_LIN1, lin1_b, (float*)nullptr, Hhi, Hlo,
         DFF, D_MODEL, 1);
    GEMM(Hhi, Hlo, Whi + W_LIN2, Wlo + W_LIN2, lin2_b, ff2,
         BF16_NULL, BF16_NULL, D_MODEL, DFF, 0);

    // 10) out = LN2(x2 + ff)
    add_ln_kernel<<<NTOK, 256>>>(x2, ff2, nullptr, n2_g, n2_b, out);
}